// round 6
// baseline (speedup 1.0000x reference)
#include <cuda_runtime.h>
#include <cuda_bf16.h>

// Problem constants (fixed shapes from reference)
#define NN 50000
#define NE 800000
#define DD 96

#define SCAN_B 1024
#define SCAN_NB ((NN + SCAN_B - 1) / SCAN_B)   // 49

// ---- device scratch (no runtime allocation allowed) ----
__device__ int   g_deg[NN];
__device__ float g_dinv[NN];
__device__ int   g_rowptr[NN + 1];
__device__ int   g_cursor[NN];
__device__ int   g_col[NE];
__device__ int   g_partial[SCAN_NB];
__device__ int   g_partoff[SCAN_NB];
__device__ int   g_is64;          // 1 if edge_index is int64, 0 if int32
__device__ float g_h[NN * DD];    // GEMM output (pre-aggregation)
__device__ float g_hp[NN * DD];   // post layer-1 activation

// ---------------------------------------------------------------------------
// dtype detection: interpret the first NE int64 slots of the edge buffer.
// If edge_index is int32, those 8*NE bytes are exactly the whole buffer
// (2*NE*4), so no OOB read either way. int32 data read as int64 packs two
// indices -> values >= 2^32 whenever the high word (the next index) != 0,
// which happens with certainty over 800k random indices.
// ---------------------------------------------------------------------------
__global__ void k_detect(const void* __restrict__ ei_raw) {
    const long long* p64 = (const long long*)ei_raw;
    int e = blockIdx.x * blockDim.x + threadIdx.x;
    if (e < NE) {
        long long v = p64[e];
        if (v < 0 || v >= NN) atomicAnd(&g_is64, 0);
    }
}

__device__ __forceinline__ void load_edge(const void* ei_raw, int e, int& s, int& d) {
    if (g_is64) {
        const long long* p = (const long long*)ei_raw;
        s = (int)p[e];
        d = (int)p[NE + e];
    } else {
        const int* p = (const int*)ei_raw;
        s = p[e];
        d = p[NE + e];
    }
}

// ---------------------------------------------------------------------------
// degree (with self loop), dinv
// ---------------------------------------------------------------------------
__global__ void k_init() {
    int i = blockIdx.x * blockDim.x + threadIdx.x;
    if (i < NN) g_deg[i] = 1;  // self loop
    if (i == 0) g_is64 = 1;    // detection kernel clears if invalid as int64
}

__global__ void k_count_deg(const void* __restrict__ ei_raw) {
    int e = blockIdx.x * blockDim.x + threadIdx.x;
    if (e < NE) {
        int s, d;
        load_edge(ei_raw, e, s, d);
        if ((unsigned)d < NN) atomicAdd(&g_deg[d], 1);   // bounds guard: never trap
    }
}

__global__ void k_dinv() {
    int i = blockIdx.x * blockDim.x + threadIdx.x;
    if (i < NN) g_dinv[i] = rsqrtf((float)g_deg[i]);
}

// ---------------------------------------------------------------------------
// exclusive scan of (deg[i]-1) -> rowptr  (3-kernel scan)
// ---------------------------------------------------------------------------
__global__ void k_scan_partial() {
    __shared__ int s[SCAN_B];
    int i = blockIdx.x * SCAN_B + threadIdx.x;
    int v = (i < NN) ? (g_deg[i] - 1) : 0;
    s[threadIdx.x] = v;
    __syncthreads();
    for (int off = SCAN_B / 2; off > 0; off >>= 1) {
        if (threadIdx.x < off) s[threadIdx.x] += s[threadIdx.x + off];
        __syncthreads();
    }
    if (threadIdx.x == 0) g_partial[blockIdx.x] = s[0];
}

__global__ void k_scan_offsets() {
    if (threadIdx.x == 0 && blockIdx.x == 0) {
        int acc = 0;
        for (int b = 0; b < SCAN_NB; b++) {
            g_partoff[b] = acc;
            acc += g_partial[b];
        }
    }
}

__global__ void k_scan_final() {
    __shared__ int s[SCAN_B];
    int i = blockIdx.x * SCAN_B + threadIdx.x;
    int v = (i < NN) ? (g_deg[i] - 1) : 0;
    s[threadIdx.x] = v;
    __syncthreads();
    // Hillis-Steele inclusive scan
    for (int off = 1; off < SCAN_B; off <<= 1) {
        int t = 0;
        if ((int)threadIdx.x >= off) t = s[threadIdx.x - off];
        __syncthreads();
        s[threadIdx.x] += t;
        __syncthreads();
    }
    int inc = s[threadIdx.x];
    int base = g_partoff[blockIdx.x];
    if (i < NN) {
        g_rowptr[i] = base + inc - v;  // exclusive
        g_cursor[i] = base + inc - v;  // fill cursor starts at rowptr
    }
    if (i == NN - 1) g_rowptr[NN] = base + inc;   // == NE (if all indices valid)
}

// ---------------------------------------------------------------------------
// CSR fill (order within a row is nondeterministic; only affects fp rounding)
// ---------------------------------------------------------------------------
__global__ void k_fill(const void* __restrict__ ei_raw) {
    int e = blockIdx.x * blockDim.x + threadIdx.x;
    if (e < NE) {
        int s, d;
        load_edge(ei_raw, e, s, d);
        if ((unsigned)d < NN && (unsigned)s < NN) {
            int pos = atomicAdd(&g_cursor[d], 1);
            if ((unsigned)pos < NE) g_col[pos] = s;
        }
    }
}

// ---------------------------------------------------------------------------
// GEMM:  g_h[N,96] = A[N,96] @ W[96,96]
// A == nullptr  -> read from g_hp (layer-2 input); output always g_h.
// block = (32,8), tile = 64 rows x 96 cols, W staged in 32-row smem chunks
// ---------------------------------------------------------------------------
__global__ void k_gemm96(const float* __restrict__ A,
                         const float* __restrict__ W) {
    __shared__ float xs[64][DD];     // 24 KB
    __shared__ float ws[32][DD];     // 12 KB
    const float* Ain = (A != nullptr) ? A : (const float*)g_hp;
    int row0 = blockIdx.x * 64;
    int tx = threadIdx.x, ty = threadIdx.y;
    int tid = ty * 32 + tx;

    for (int i = tid; i < 64 * DD; i += 256) {
        int r = i / DD, c = i % DD;
        int gr = row0 + r;
        xs[r][c] = (gr < NN) ? Ain[gr * DD + c] : 0.0f;
    }

    float acc[8][3];
#pragma unroll
    for (int r = 0; r < 8; r++) { acc[r][0] = 0.f; acc[r][1] = 0.f; acc[r][2] = 0.f; }

    for (int kb = 0; kb < DD; kb += 32) {
        __syncthreads();   // also covers initial xs load
        for (int i = tid; i < 32 * DD; i += 256) {
            int r = i / DD, c = i % DD;
            ws[r][c] = W[(kb + r) * DD + c];
        }
        __syncthreads();
#pragma unroll
        for (int k = 0; k < 32; k++) {
            float w0 = ws[k][tx];
            float w1 = ws[k][tx + 32];
            float w2 = ws[k][tx + 64];
#pragma unroll
            for (int r = 0; r < 8; r++) {
                float xv = xs[ty * 8 + r][kb + k];
                acc[r][0] = fmaf(xv, w0, acc[r][0]);
                acc[r][1] = fmaf(xv, w1, acc[r][1]);
                acc[r][2] = fmaf(xv, w2, acc[r][2]);
            }
        }
    }

#pragma unroll
    for (int r = 0; r < 8; r++) {
        int gr = row0 + ty * 8 + r;
        if (gr < NN) {
            g_h[gr * DD + tx]      = acc[r][0];
            g_h[gr * DD + tx + 32] = acc[r][1];
            g_h[gr * DD + tx + 64] = acc[r][2];
        }
    }
}

// ---------------------------------------------------------------------------
// Aggregation over g_h:
//   res[i,:] = dinv[i]*( dinv[i]*h[i,:] + sum_e dinv[src_e]*h[src_e,:] ) + b
// out == nullptr -> write g_hp (with PReLU); else write out (no PReLU).
// block = (96, 4): one node per y-slice, thread.x = feature.
// ---------------------------------------------------------------------------
__global__ void k_agg(const float* __restrict__ bias,
                      const float* __restrict__ a1,
                      int use_prelu,
                      float* __restrict__ out) {
    int node = blockIdx.x * blockDim.y + threadIdx.y;
    if (node >= NN) return;
    int t = threadIdx.x;          // 0..95
    float* dst = (out != nullptr) ? out : (float*)g_hp;

    float di = g_dinv[node];
    float acc = di * g_h[node * DD + t];   // self-loop term (scaled by di again below)

    int beg = g_rowptr[node];
    int end = g_rowptr[node + 1];
    for (int e = beg; e < end; e++) {
        int s = g_col[e];                  // broadcast across the group
        float ns = g_dinv[s];              // broadcast
        acc = fmaf(ns, g_h[s * DD + t], acc);
    }
    // want di*acc + bias: fmaf(di, acc, bias[t]) is exactly that
    acc = fmaf(di, acc, bias[t]);
    if (use_prelu) {
        float a = a1[0];
        acc = acc > 0.0f ? acc : a * acc;
    }
    dst[node * DD + t] = acc;
}

// ---------------------------------------------------------------------------
extern "C" void kernel_launch(void* const* d_in, const int* in_sizes, int n_in,
                              void* d_out, int out_size) {
    const float* x  = (const float*)d_in[0];
    const void*  ei = (const void*)d_in[1];      // int64 OR int32, detected on device
    const float* W1 = (const float*)d_in[2];
    const float* b1 = (const float*)d_in[3];
    const float* a1 = (const float*)d_in[4];
    const float* W2 = (const float*)d_in[5];
    const float* b2 = (const float*)d_in[6];
    float*       out = (float*)d_out;

    // ---- graph structure prep ----
    k_init<<<(NN + 255) / 256, 256>>>();
    k_detect<<<(NE + 255) / 256, 256>>>(ei);
    k_count_deg<<<(NE + 255) / 256, 256>>>(ei);
    k_dinv<<<(NN + 255) / 256, 256>>>();
    k_scan_partial<<<SCAN_NB, SCAN_B>>>();
    k_scan_offsets<<<1, 32>>>();
    k_scan_final<<<SCAN_NB, SCAN_B>>>();
    k_fill<<<(NE + 255) / 256, 256>>>(ei);

    dim3 gB(32, 8);
    int gemmGrid = (NN + 63) / 64;
    dim3 aB(96, 4);
    int aggGrid = (NN + 3) / 4;

    // ---- layer 1 ----
    k_gemm96<<<gemmGrid, gB>>>(x, W1);
    k_agg<<<aggGrid, aB>>>(b1, a1, 1, nullptr);   // -> g_hp (PReLU)

    // ---- layer 2 ----
    k_gemm96<<<gemmGrid, gB>>>(nullptr, W2);      // reads g_hp
    k_agg<<<aggGrid, aB>>>(b2, a1, 0, out);       // -> d_out
}

// round 7
// speedup vs baseline: 1.0333x; 1.0333x over previous
#include <cuda_runtime.h>
#include <cuda_bf16.h>

// Problem constants (fixed shapes from reference)
#define NN 50000
#define NE 800000
#define DD 96
#define D4 (DD / 4)   // 24 float4 per row

#define SCAN_B 1024
#define SCAN_NB ((NN + SCAN_B - 1) / SCAN_B)   // 49

// ---- device scratch (no runtime allocation allowed) ----
__device__ int   g_deg[NN];
__device__ float g_dinv[NN];
__device__ int   g_rowptr[NN + 1];
__device__ int   g_cursor[NN];
__device__ int   g_col[NE];
__device__ int   g_partial[SCAN_NB];
__device__ int   g_partoff[SCAN_NB];
__device__ int   g_is64;          // 1 if edge_index is int64, 0 if int32
__device__ float g_h[NN * DD];    // GEMM output (pre-aggregation)
__device__ float g_hp[NN * DD];   // post layer-1 activation

// ---------------------------------------------------------------------------
// dtype detection (int64 vs silently-int32 edge_index). Reading the first NE
// int64 slots covers exactly the int32 buffer size, so no OOB either way.
// ---------------------------------------------------------------------------
__global__ void k_detect(const void* __restrict__ ei_raw) {
    const long long* p64 = (const long long*)ei_raw;
    int e = blockIdx.x * blockDim.x + threadIdx.x;
    if (e < NE) {
        long long v = p64[e];
        if (v < 0 || v >= NN) atomicAnd(&g_is64, 0);
    }
}

__device__ __forceinline__ void load_edge(const void* ei_raw, int e, int& s, int& d) {
    if (g_is64) {
        const long long* p = (const long long*)ei_raw;
        s = (int)p[e];
        d = (int)p[NE + e];
    } else {
        const int* p = (const int*)ei_raw;
        s = p[e];
        d = p[NE + e];
    }
}

// ---------------------------------------------------------------------------
// degree (with self loop), dinv
// ---------------------------------------------------------------------------
__global__ void k_init() {
    int i = blockIdx.x * blockDim.x + threadIdx.x;
    if (i < NN) g_deg[i] = 1;  // self loop
    if (i == 0) g_is64 = 1;
}

__global__ void k_count_deg(const void* __restrict__ ei_raw) {
    int e = blockIdx.x * blockDim.x + threadIdx.x;
    if (e < NE) {
        int s, d;
        load_edge(ei_raw, e, s, d);
        if ((unsigned)d < NN) atomicAdd(&g_deg[d], 1);
    }
}

__global__ void k_dinv() {
    int i = blockIdx.x * blockDim.x + threadIdx.x;
    if (i < NN) g_dinv[i] = rsqrtf((float)g_deg[i]);
}

// ---------------------------------------------------------------------------
// exclusive scan of (deg[i]-1) -> rowptr  (3-kernel scan)
// ---------------------------------------------------------------------------
__global__ void k_scan_partial() {
    __shared__ int s[SCAN_B];
    int i = blockIdx.x * SCAN_B + threadIdx.x;
    int v = (i < NN) ? (g_deg[i] - 1) : 0;
    s[threadIdx.x] = v;
    __syncthreads();
    for (int off = SCAN_B / 2; off > 0; off >>= 1) {
        if (threadIdx.x < off) s[threadIdx.x] += s[threadIdx.x + off];
        __syncthreads();
    }
    if (threadIdx.x == 0) g_partial[blockIdx.x] = s[0];
}

__global__ void k_scan_offsets() {
    if (threadIdx.x == 0 && blockIdx.x == 0) {
        int acc = 0;
        for (int b = 0; b < SCAN_NB; b++) {
            g_partoff[b] = acc;
            acc += g_partial[b];
        }
    }
}

__global__ void k_scan_final() {
    __shared__ int s[SCAN_B];
    int i = blockIdx.x * SCAN_B + threadIdx.x;
    int v = (i < NN) ? (g_deg[i] - 1) : 0;
    s[threadIdx.x] = v;
    __syncthreads();
    for (int off = 1; off < SCAN_B; off <<= 1) {
        int t = 0;
        if ((int)threadIdx.x >= off) t = s[threadIdx.x - off];
        __syncthreads();
        s[threadIdx.x] += t;
        __syncthreads();
    }
    int inc = s[threadIdx.x];
    int base = g_partoff[blockIdx.x];
    if (i < NN) {
        g_rowptr[i] = base + inc - v;
        g_cursor[i] = base + inc - v;
    }
    if (i == NN - 1) g_rowptr[NN] = base + inc;
}

// ---------------------------------------------------------------------------
// CSR fill
// ---------------------------------------------------------------------------
__global__ void k_fill(const void* __restrict__ ei_raw) {
    int e = blockIdx.x * blockDim.x + threadIdx.x;
    if (e < NE) {
        int s, d;
        load_edge(ei_raw, e, s, d);
        if ((unsigned)d < NN && (unsigned)s < NN) {
            int pos = atomicAdd(&g_cursor[d], 1);
            if ((unsigned)pos < NE) g_col[pos] = s;
        }
    }
}

// ---------------------------------------------------------------------------
// GEMM:  g_h[N,96] = A[N,96] @ W[96,96]
// A == nullptr -> read from g_hp. block=(32,8), tile = 64 rows.
// ---------------------------------------------------------------------------
__global__ void k_gemm96(const float* __restrict__ A,
                         const float* __restrict__ W) {
    __shared__ float xs[64][DD];
    __shared__ float ws[32][DD];
    const float* Ain = (A != nullptr) ? A : (const float*)g_hp;
    int row0 = blockIdx.x * 64;
    int tx = threadIdx.x, ty = threadIdx.y;
    int tid = ty * 32 + tx;

    for (int i = tid; i < 64 * DD; i += 256) {
        int r = i / DD, c = i % DD;
        int gr = row0 + r;
        xs[r][c] = (gr < NN) ? Ain[gr * DD + c] : 0.0f;
    }

    float acc[8][3];
#pragma unroll
    for (int r = 0; r < 8; r++) { acc[r][0] = 0.f; acc[r][1] = 0.f; acc[r][2] = 0.f; }

    for (int kb = 0; kb < DD; kb += 32) {
        __syncthreads();
        for (int i = tid; i < 32 * DD; i += 256) {
            int r = i / DD, c = i % DD;
            ws[r][c] = W[(kb + r) * DD + c];
        }
        __syncthreads();
#pragma unroll
        for (int k = 0; k < 32; k++) {
            float w0 = ws[k][tx];
            float w1 = ws[k][tx + 32];
            float w2 = ws[k][tx + 64];
#pragma unroll
            for (int r = 0; r < 8; r++) {
                float xv = xs[ty * 8 + r][kb + k];
                acc[r][0] = fmaf(xv, w0, acc[r][0]);
                acc[r][1] = fmaf(xv, w1, acc[r][1]);
                acc[r][2] = fmaf(xv, w2, acc[r][2]);
            }
        }
    }

#pragma unroll
    for (int r = 0; r < 8; r++) {
        int gr = row0 + ty * 8 + r;
        if (gr < NN) {
            g_h[gr * DD + tx]      = acc[r][0];
            g_h[gr * DD + tx + 32] = acc[r][1];
            g_h[gr * DD + tx + 64] = acc[r][2];
        }
    }
}

// ---------------------------------------------------------------------------
// Aggregation v2: warp-per-node, float4 gathers, shuffle-broadcast indices.
//   res[i,:] = dinv[i]*( dinv[i]*h[i,:] + sum_e dinv[s_e]*h[s_e,:] ) + b
// out == nullptr -> g_hp (with PReLU); else out (no PReLU).
// Lanes 0..31 cooperatively fetch (col, dinv) for a chunk of <=32 edges,
// then all j-iterations issue INDEPENDENT float4 row gathers (lane<24).
// ---------------------------------------------------------------------------
__global__ void k_agg(const float* __restrict__ bias,
                      const float* __restrict__ a1,
                      int use_prelu,
                      float* __restrict__ out) {
    int gwarp = (blockIdx.x * blockDim.x + threadIdx.x) >> 5;
    int lane  = threadIdx.x & 31;
    if (gwarp >= NN) return;
    int node = gwarp;

    const float4* h4 = (const float4*)g_h;
    float4* dst4 = (out != nullptr) ? (float4*)out : (float4*)g_hp;

    float di = g_dinv[node];
    bool active = lane < D4;

    float4 acc = make_float4(0.f, 0.f, 0.f, 0.f);
    if (active) {
        float4 v = h4[node * D4 + lane];
        acc.x = di * v.x; acc.y = di * v.y; acc.z = di * v.z; acc.w = di * v.w;
    }

    int beg = g_rowptr[node];
    int end = g_rowptr[node + 1];

    for (int base = beg; base < end; base += 32) {
        int e = base + lane;
        int s = 0;
        float ns = 0.f;
        if (e < end) {
            s = g_col[e];
            ns = g_dinv[s];
        }
        int cnt = min(32, end - base);

        int j = 0;
        // unrolled by 4: four independent gathers in flight per step
        for (; j + 4 <= cnt; j += 4) {
            int   s0 = __shfl_sync(0xffffffffu, s,  j + 0);
            int   s1 = __shfl_sync(0xffffffffu, s,  j + 1);
            int   s2 = __shfl_sync(0xffffffffu, s,  j + 2);
            int   s3 = __shfl_sync(0xffffffffu, s,  j + 3);
            float n0 = __shfl_sync(0xffffffffu, ns, j + 0);
            float n1 = __shfl_sync(0xffffffffu, ns, j + 1);
            float n2 = __shfl_sync(0xffffffffu, ns, j + 2);
            float n3 = __shfl_sync(0xffffffffu, ns, j + 3);
            if (active) {
                float4 v0 = h4[s0 * D4 + lane];
                float4 v1 = h4[s1 * D4 + lane];
                float4 v2 = h4[s2 * D4 + lane];
                float4 v3 = h4[s3 * D4 + lane];
                acc.x = fmaf(n0, v0.x, acc.x); acc.y = fmaf(n0, v0.y, acc.y);
                acc.z = fmaf(n0, v0.z, acc.z); acc.w = fmaf(n0, v0.w, acc.w);
                acc.x = fmaf(n1, v1.x, acc.x); acc.y = fmaf(n1, v1.y, acc.y);
                acc.z = fmaf(n1, v1.z, acc.z); acc.w = fmaf(n1, v1.w, acc.w);
                acc.x = fmaf(n2, v2.x, acc.x); acc.y = fmaf(n2, v2.y, acc.y);
                acc.z = fmaf(n2, v2.z, acc.z); acc.w = fmaf(n2, v2.w, acc.w);
                acc.x = fmaf(n3, v3.x, acc.x); acc.y = fmaf(n3, v3.y, acc.y);
                acc.z = fmaf(n3, v3.z, acc.z); acc.w = fmaf(n3, v3.w, acc.w);
            }
        }
        for (; j < cnt; j++) {
            int   sj = __shfl_sync(0xffffffffu, s,  j);
            float nj = __shfl_sync(0xffffffffu, ns, j);
            if (active) {
                float4 v = h4[sj * D4 + lane];
                acc.x = fmaf(nj, v.x, acc.x); acc.y = fmaf(nj, v.y, acc.y);
                acc.z = fmaf(nj, v.z, acc.z); acc.w = fmaf(nj, v.w, acc.w);
            }
        }
    }

    if (active) {
        float4 b4 = ((const float4*)bias)[lane];
        float4 r;
        r.x = fmaf(di, acc.x, b4.x);
        r.y = fmaf(di, acc.y, b4.y);
        r.z = fmaf(di, acc.z, b4.z);
        r.w = fmaf(di, acc.w, b4.w);
        if (use_prelu) {
            float a = a1[0];
            r.x = r.x > 0.f ? r.x : a * r.x;
            r.y = r.y > 0.f ? r.y : a * r.y;
            r.z = r.z > 0.f ? r.z : a * r.z;
            r.w = r.w > 0.f ? r.w : a * r.w;
        }
        dst4[node * D4 + lane] = r;
    }
}

// ---------------------------------------------------------------------------
extern "C" void kernel_launch(void* const* d_in, const int* in_sizes, int n_in,
                              void* d_out, int out_size) {
    const float* x  = (const float*)d_in[0];
    const void*  ei = (const void*)d_in[1];
    const float* W1 = (const float*)d_in[2];
    const float* b1 = (const float*)d_in[3];
    const float* a1 = (const float*)d_in[4];
    const float* W2 = (const float*)d_in[5];
    const float* b2 = (const float*)d_in[6];
    float*       out = (float*)d_out;

    // ---- graph structure prep ----
    k_init<<<(NN + 255) / 256, 256>>>();
    k_detect<<<(NE + 255) / 256, 256>>>(ei);
    k_count_deg<<<(NE + 255) / 256, 256>>>(ei);
    k_dinv<<<(NN + 255) / 256, 256>>>();
    k_scan_partial<<<SCAN_NB, SCAN_B>>>();
    k_scan_offsets<<<1, 32>>>();
    k_scan_final<<<SCAN_NB, SCAN_B>>>();
    k_fill<<<(NE + 255) / 256, 256>>>(ei);

    dim3 gB(32, 8);
    int gemmGrid = (NN + 63) / 64;
    // k_agg: warp per node, 256 threads = 8 warps per block
    int aggGrid = (NN + 7) / 8;

    // ---- layer 1 ----
    k_gemm96<<<gemmGrid, gB>>>(x, W1);
    k_agg<<<aggGrid, 256>>>(b1, a1, 1, nullptr);   // -> g_hp (PReLU)

    // ---- layer 2 ----
    k_gemm96<<<gemmGrid, gB>>>(nullptr, W2);       // reads g_hp
    k_agg<<<aggGrid, 256>>>(b2, a1, 0, out);       // -> d_out
}

// round 9
// speedup vs baseline: 4.0737x; 3.9424x over previous
#include <cuda_runtime.h>
#include <cuda_bf16.h>

// Problem constants (fixed shapes from reference)
#define NN 50000
#define NE 800000
#define DD 96
#define D4 (DD / 4)   // 24 float4 per row

#define SCAN_B 1024
#define SCAN_NB ((NN + SCAN_B - 1) / SCAN_B)   // 49

// ---- device scratch (no runtime allocation allowed) ----
__device__ int   g_deg[NN];
__device__ float g_dinv[NN];
__device__ int   g_rowptr[NN + 1];
__device__ int   g_cursor[NN];
__device__ int   g_col[NE];
__device__ int   g_partial[SCAN_NB];
__device__ int   g_partoff[SCAN_NB];
__device__ int   g_is64;          // 1 if edge_index is int64, 0 if int32
__device__ float g_h[NN * DD];    // GEMM output (pre-aggregation)
__device__ float g_hp[NN * DD];   // post layer-1 activation

// ---------------------------------------------------------------------------
// init: degree = 1 (self loop)
// ---------------------------------------------------------------------------
__global__ void k_init() {
    int i = blockIdx.x * blockDim.x + threadIdx.x;
    if (i < NN) g_deg[i] = 1;
}

// ---------------------------------------------------------------------------
// dtype detection, single block. Sample 16K int64-slots spread across the
// buffer; int32 data interpreted as int64 packs (idx[2k+1]<<32)|idx[2k],
// which lands outside [0,NN) unless the high index is 0 (p = 1/50000 per
// sample) -> 16K samples decide with certainty. Writes g_is64 race-free.
// ---------------------------------------------------------------------------
#define DET_T 1024
#define DET_SAMP 16
__global__ void k_detect(const void* __restrict__ ei_raw) {
    __shared__ int bad;
    if (threadIdx.x == 0) bad = 0;
    __syncthreads();
    const long long* p64 = (const long long*)ei_raw;
    int stride = NE / (DET_T * DET_SAMP);   // ~48
    int myBad = 0;
    for (int j = 0; j < DET_SAMP; j++) {
        int e = (threadIdx.x * DET_SAMP + j) * stride;
        if (e < NE) {
            long long v = p64[e];
            if (v < 0 || v >= NN) myBad = 1;
        }
    }
    if (myBad) atomicOr(&bad, 1);
    __syncthreads();
    if (threadIdx.x == 0) g_is64 = bad ? 0 : 1;
}

__device__ __forceinline__ void load_edge(const void* ei_raw, int e, int& s, int& d) {
    if (g_is64) {
        const long long* p = (const long long*)ei_raw;
        s = (int)p[e];
        d = (int)p[NE + e];
    } else {
        const int* p = (const int*)ei_raw;
        s = p[e];
        d = p[NE + e];
    }
}

// ---------------------------------------------------------------------------
// degree count
// ---------------------------------------------------------------------------
__global__ void k_count_deg(const void* __restrict__ ei_raw) {
    int e = blockIdx.x * blockDim.x + threadIdx.x;
    if (e < NE) {
        int s, d;
        load_edge(ei_raw, e, s, d);
        if ((unsigned)d < NN) atomicAdd(&g_deg[d], 1);
    }
}

// ---------------------------------------------------------------------------
// fused: per-block sum of (deg-1) for scan, plus dinv = rsqrt(deg)
// ---------------------------------------------------------------------------
__global__ void k_scanpartial_dinv() {
    __shared__ int s[SCAN_B];
    int i = blockIdx.x * SCAN_B + threadIdx.x;
    int dg = (i < NN) ? g_deg[i] : 1;
    if (i < NN) g_dinv[i] = rsqrtf((float)dg);
    int v = (i < NN) ? (dg - 1) : 0;
    s[threadIdx.x] = v;
    __syncthreads();
    for (int off = SCAN_B / 2; off > 0; off >>= 1) {
        if (threadIdx.x < off) s[threadIdx.x] += s[threadIdx.x + off];
        __syncthreads();
    }
    if (threadIdx.x == 0) g_partial[blockIdx.x] = s[0];
}

// ---------------------------------------------------------------------------
// exclusive scan of the 49 block partials — single warp, shuffle scan
// ---------------------------------------------------------------------------
__global__ void k_scan_offsets() {
    int lane = threadIdx.x;           // one warp
    int v0 = (lane < SCAN_NB) ? g_partial[lane] : 0;
    int v1 = (32 + lane < SCAN_NB) ? g_partial[32 + lane] : 0;
    int i0 = v0;
#pragma unroll
    for (int off = 1; off < 32; off <<= 1) {
        int t = __shfl_up_sync(0xffffffffu, i0, off);
        if (lane >= off) i0 += t;
    }
    int total0 = __shfl_sync(0xffffffffu, i0, 31);
    int i1 = v1;
#pragma unroll
    for (int off = 1; off < 32; off <<= 1) {
        int t = __shfl_up_sync(0xffffffffu, i1, off);
        if (lane >= off) i1 += t;
    }
    if (lane < SCAN_NB) g_partoff[lane] = i0 - v0;
    if (32 + lane < SCAN_NB) g_partoff[32 + lane] = total0 + i1 - v1;
}

__global__ void k_scan_final() {
    __shared__ int s[SCAN_B];
    int i = blockIdx.x * SCAN_B + threadIdx.x;
    int v = (i < NN) ? (g_deg[i] - 1) : 0;
    s[threadIdx.x] = v;
    __syncthreads();
    for (int off = 1; off < SCAN_B; off <<= 1) {
        int t = 0;
        if ((int)threadIdx.x >= off) t = s[threadIdx.x - off];
        __syncthreads();
        s[threadIdx.x] += t;
        __syncthreads();
    }
    int inc = s[threadIdx.x];
    int base = g_partoff[blockIdx.x];
    if (i < NN) {
        g_rowptr[i] = base + inc - v;
        g_cursor[i] = base + inc - v;
    }
    if (i == NN - 1) g_rowptr[NN] = base + inc;
}

// ---------------------------------------------------------------------------
// CSR fill
// ---------------------------------------------------------------------------
__global__ void k_fill(const void* __restrict__ ei_raw) {
    int e = blockIdx.x * blockDim.x + threadIdx.x;
    if (e < NE) {
        int s, d;
        load_edge(ei_raw, e, s, d);
        if ((unsigned)d < NN && (unsigned)s < NN) {
            int pos = atomicAdd(&g_cursor[d], 1);
            if ((unsigned)pos < NE) g_col[pos] = s;
        }
    }
}

// ---------------------------------------------------------------------------
// GEMM (UNCHANGED — now sits in the profiled launch slot for diagnosis):
//   g_h[N,96] = A[N,96] @ W[96,96];  A==nullptr -> read g_hp
// ---------------------------------------------------------------------------
__global__ void k_gemm96(const float* __restrict__ A,
                         const float* __restrict__ W) {
    __shared__ float xs[64][DD];
    __shared__ float ws[32][DD];
    const float* Ain = (A != nullptr) ? A : (const float*)g_hp;
    int row0 = blockIdx.x * 64;
    int tx = threadIdx.x, ty = threadIdx.y;
    int tid = ty * 32 + tx;

    for (int i = tid; i < 64 * DD; i += 256) {
        int r = i / DD, c = i % DD;
        int gr = row0 + r;
        xs[r][c] = (gr < NN) ? Ain[gr * DD + c] : 0.0f;
    }

    float acc[8][3];
#pragma unroll
    for (int r = 0; r < 8; r++) { acc[r][0] = 0.f; acc[r][1] = 0.f; acc[r][2] = 0.f; }

    for (int kb = 0; kb < DD; kb += 32) {
        __syncthreads();
        for (int i = tid; i < 32 * DD; i += 256) {
            int r = i / DD, c = i % DD;
            ws[r][c] = W[(kb + r) * DD + c];
        }
        __syncthreads();
#pragma unroll
        for (int k = 0; k < 32; k++) {
            float w0 = ws[k][tx];
            float w1 = ws[k][tx + 32];
            float w2 = ws[k][tx + 64];
#pragma unroll
            for (int r = 0; r < 8; r++) {
                float xv = xs[ty * 8 + r][kb + k];
                acc[r][0] = fmaf(xv, w0, acc[r][0]);
                acc[r][1] = fmaf(xv, w1, acc[r][1]);
                acc[r][2] = fmaf(xv, w2, acc[r][2]);
            }
        }
    }

#pragma unroll
    for (int r = 0; r < 8; r++) {
        int gr = row0 + ty * 8 + r;
        if (gr < NN) {
            g_h[gr * DD + tx]      = acc[r][0];
            g_h[gr * DD + tx + 32] = acc[r][1];
            g_h[gr * DD + tx + 64] = acc[r][2];
        }
    }
}

// ---------------------------------------------------------------------------
// Aggregation (unchanged v2): warp-per-node, float4 gathers, shuffle bcast.
// ---------------------------------------------------------------------------
__global__ void k_agg(const float* __restrict__ bias,
                      const float* __restrict__ a1,
                      int use_prelu,
                      float* __restrict__ out) {
    int gwarp = (blockIdx.x * blockDim.x + threadIdx.x) >> 5;
    int lane  = threadIdx.x & 31;
    if (gwarp >= NN) return;
    int node = gwarp;

    const float4* h4 = (const float4*)g_h;
    float4* dst4 = (out != nullptr) ? (float4*)out : (float4*)g_hp;

    float di = g_dinv[node];
    bool active = lane < D4;

    float4 acc = make_float4(0.f, 0.f, 0.f, 0.f);
    if (active) {
        float4 v = h4[node * D4 + lane];
        acc.x = di * v.x; acc.y = di * v.y; acc.z = di * v.z; acc.w = di * v.w;
    }

    int beg = g_rowptr[node];
    int end = g_rowptr[node + 1];

    for (int base = beg; base < end; base += 32) {
        int e = base + lane;
        int s = 0;
        float ns = 0.f;
        if (e < end) {
            s = g_col[e];
            ns = g_dinv[s];
        }
        int cnt = min(32, end - base);

        int j = 0;
        for (; j + 4 <= cnt; j += 4) {
            int   s0 = __shfl_sync(0xffffffffu, s,  j + 0);
            int   s1 = __shfl_sync(0xffffffffu, s,  j + 1);
            int   s2 = __shfl_sync(0xffffffffu, s,  j + 2);
            int   s3 = __shfl_sync(0xffffffffu, s,  j + 3);
            float n0 = __shfl_sync(0xffffffffu, ns, j + 0);
            float n1 = __shfl_sync(0xffffffffu, ns, j + 1);
            float n2 = __shfl_sync(0xffffffffu, ns, j + 2);
            float n3 = __shfl_sync(0xffffffffu, ns, j + 3);
            if (active) {
                float4 v0 = h4[s0 * D4 + lane];
                float4 v1 = h4[s1 * D4 + lane];
                float4 v2 = h4[s2 * D4 + lane];
                float4 v3 = h4[s3 * D4 + lane];
                acc.x = fmaf(n0, v0.x, acc.x); acc.y = fmaf(n0, v0.y, acc.y);
                acc.z = fmaf(n0, v0.z, acc.z); acc.w = fmaf(n0, v0.w, acc.w);
                acc.x = fmaf(n1, v1.x, acc.x); acc.y = fmaf(n1, v1.y, acc.y);
                acc.z = fmaf(n1, v1.z, acc.z); acc.w = fmaf(n1, v1.w, acc.w);
                acc.x = fmaf(n2, v2.x, acc.x); acc.y = fmaf(n2, v2.y, acc.y);
                acc.z = fmaf(n2, v2.z, acc.z); acc.w = fmaf(n2, v2.w, acc.w);
                acc.x = fmaf(n3, v3.x, acc.x); acc.y = fmaf(n3, v3.y, acc.y);
                acc.z = fmaf(n3, v3.z, acc.z); acc.w = fmaf(n3, v3.w, acc.w);
            }
        }
        for (; j < cnt; j++) {
            int   sj = __shfl_sync(0xffffffffu, s,  j);
            float nj = __shfl_sync(0xffffffffu, ns, j);
            if (active) {
                float4 v = h4[sj * D4 + lane];
                acc.x = fmaf(nj, v.x, acc.x); acc.y = fmaf(nj, v.y, acc.y);
                acc.z = fmaf(nj, v.z, acc.z); acc.w = fmaf(nj, v.w, acc.w);
            }
        }
    }

    if (active) {
        float4 b4 = ((const float4*)bias)[lane];
        float4 r;
        r.x = fmaf(di, acc.x, b4.x);
        r.y = fmaf(di, acc.y, b4.y);
        r.z = fmaf(di, acc.z, b4.z);
        r.w = fmaf(di, acc.w, b4.w);
        if (use_prelu) {
            float a = a1[0];
            r.x = r.x > 0.f ? r.x : a * r.x;
            r.y = r.y > 0.f ? r.y : a * r.y;
            r.z = r.z > 0.f ? r.z : a * r.z;
            r.w = r.w > 0.f ? r.w : a * r.w;
        }
        dst4[node * D4 + lane] = r;
    }
}

// ---------------------------------------------------------------------------
extern "C" void kernel_launch(void* const* d_in, const int* in_sizes, int n_in,
                              void* d_out, int out_size) {
    const float* x  = (const float*)d_in[0];
    const void*  ei = (const void*)d_in[1];
    const float* W1 = (const float*)d_in[2];
    const float* b1 = (const float*)d_in[3];
    const float* a1 = (const float*)d_in[4];
    const float* W2 = (const float*)d_in[5];
    const float* b2 = (const float*)d_in[6];
    float*       out = (float*)d_out;

    dim3 gB(32, 8);
    int gemmGrid = (NN + 63) / 64;
    int aggGrid = (NN + 7) / 8;   // warp per node, 8 warps/block

    // launch idx:  0         1         2            3 (profiled slot)
    k_init<<<(NN + 255) / 256, 256>>>();
    k_detect<<<1, DET_T>>>(ei);
    k_count_deg<<<(NE + 255) / 256, 256>>>(ei);
    k_gemm96<<<gemmGrid, gB>>>(x, W1);             // layer-1 GEMM: independent of CSR

    //              4                  5            6            7
    k_scanpartial_dinv<<<SCAN_NB, SCAN_B>>>();
    k_scan_offsets<<<1, 32>>>();
    k_scan_final<<<SCAN_NB, SCAN_B>>>();
    k_fill<<<(NE + 255) / 256, 256>>>(ei);

    //              8                  9            10
    k_agg<<<aggGrid, 256>>>(b1, a1, 1, nullptr);   // -> g_hp (PReLU)
    k_gemm96<<<gemmGrid, gB>>>(nullptr, W2);       // reads g_hp
    k_agg<<<aggGrid, 256>>>(b2, a1, 0, out);       // -> d_out
}

// round 10
// speedup vs baseline: 4.0827x; 1.0022x over previous
#include <cuda_runtime.h>
#include <cuda_bf16.h>

// Problem constants (fixed shapes from reference)
#define NN 50000
#define NE 800000
#define DD 96
#define D4 (DD / 4)   // 24 float4 per row

#define SCAN_B 1024
#define SCAN_NB ((NN + SCAN_B - 1) / SCAN_B)   // 49

// ---- device scratch (no runtime allocation allowed) ----
__device__ int   g_deg[NN];
__device__ float g_dinv[NN];
__device__ int   g_rowptr[NN + 1];
__device__ int   g_cursor[NN];
__device__ int   g_col[NE];
__device__ int   g_partial[SCAN_NB];
__device__ int   g_partoff[SCAN_NB];
__device__ int   g_is64;          // 1 if edge_index is int64, 0 if int32
__device__ float g_h[NN * DD];    // GEMM output (pre-aggregation)
__device__ float g_hp[NN * DD];   // post layer-1 activation

// ---------------------------------------------------------------------------
// init: degree = 1 (self loop)
// ---------------------------------------------------------------------------
__global__ void k_init() {
    int i = blockIdx.x * blockDim.x + threadIdx.x;
    if (i < NN) g_deg[i] = 1;
}

// ---------------------------------------------------------------------------
// dtype detection, single block, sampled (16K int64-slot probes).
// ---------------------------------------------------------------------------
#define DET_T 1024
#define DET_SAMP 16
__global__ void k_detect(const void* __restrict__ ei_raw) {
    __shared__ int bad;
    if (threadIdx.x == 0) bad = 0;
    __syncthreads();
    const long long* p64 = (const long long*)ei_raw;
    int stride = NE / (DET_T * DET_SAMP);   // ~48
    int myBad = 0;
    for (int j = 0; j < DET_SAMP; j++) {
        int e = (threadIdx.x * DET_SAMP + j) * stride;
        if (e < NE) {
            long long v = p64[e];
            if (v < 0 || v >= NN) myBad = 1;
        }
    }
    if (myBad) atomicOr(&bad, 1);
    __syncthreads();
    if (threadIdx.x == 0) g_is64 = bad ? 0 : 1;
}

__device__ __forceinline__ void load_edge(const void* ei_raw, int e, int& s, int& d) {
    if (g_is64) {
        const long long* p = (const long long*)ei_raw;
        s = (int)p[e];
        d = (int)p[NE + e];
    } else {
        const int* p = (const int*)ei_raw;
        s = p[e];
        d = p[NE + e];
    }
}

// ---------------------------------------------------------------------------
// degree count
// ---------------------------------------------------------------------------
__global__ void k_count_deg(const void* __restrict__ ei_raw) {
    int e = blockIdx.x * blockDim.x + threadIdx.x;
    if (e < NE) {
        int s, d;
        load_edge(ei_raw, e, s, d);
        if ((unsigned)d < NN) atomicAdd(&g_deg[d], 1);
    }
}

// ---------------------------------------------------------------------------
// fused: per-block sum of (deg-1) for scan, plus dinv = rsqrt(deg)
// ---------------------------------------------------------------------------
__global__ void k_scanpartial_dinv() {
    __shared__ int s[SCAN_B];
    int i = blockIdx.x * SCAN_B + threadIdx.x;
    int dg = (i < NN) ? g_deg[i] : 1;
    if (i < NN) g_dinv[i] = rsqrtf((float)dg);
    int v = (i < NN) ? (dg - 1) : 0;
    s[threadIdx.x] = v;
    __syncthreads();
    for (int off = SCAN_B / 2; off > 0; off >>= 1) {
        if (threadIdx.x < off) s[threadIdx.x] += s[threadIdx.x + off];
        __syncthreads();
    }
    if (threadIdx.x == 0) g_partial[blockIdx.x] = s[0];
}

// ---------------------------------------------------------------------------
// exclusive scan of the 49 block partials — single warp, shuffle scan
// ---------------------------------------------------------------------------
__global__ void k_scan_offsets() {
    int lane = threadIdx.x;           // one warp
    int v0 = (lane < SCAN_NB) ? g_partial[lane] : 0;
    int v1 = (32 + lane < SCAN_NB) ? g_partial[32 + lane] : 0;
    int i0 = v0;
#pragma unroll
    for (int off = 1; off < 32; off <<= 1) {
        int t = __shfl_up_sync(0xffffffffu, i0, off);
        if (lane >= off) i0 += t;
    }
    int total0 = __shfl_sync(0xffffffffu, i0, 31);
    int i1 = v1;
#pragma unroll
    for (int off = 1; off < 32; off <<= 1) {
        int t = __shfl_up_sync(0xffffffffu, i1, off);
        if (lane >= off) i1 += t;
    }
    if (lane < SCAN_NB) g_partoff[lane] = i0 - v0;
    if (32 + lane < SCAN_NB) g_partoff[32 + lane] = total0 + i1 - v1;
}

__global__ void k_scan_final() {
    __shared__ int s[SCAN_B];
    int i = blockIdx.x * SCAN_B + threadIdx.x;
    int v = (i < NN) ? (g_deg[i] - 1) : 0;
    s[threadIdx.x] = v;
    __syncthreads();
    for (int off = 1; off < SCAN_B; off <<= 1) {
        int t = 0;
        if ((int)threadIdx.x >= off) t = s[threadIdx.x - off];
        __syncthreads();
        s[threadIdx.x] += t;
        __syncthreads();
    }
    int inc = s[threadIdx.x];
    int base = g_partoff[blockIdx.x];
    if (i < NN) {
        g_rowptr[i] = base + inc - v;
        g_cursor[i] = base + inc - v;
    }
    if (i == NN - 1) g_rowptr[NN] = base + inc;
}

// ---------------------------------------------------------------------------
// CSR fill
// ---------------------------------------------------------------------------
__global__ void k_fill(const void* __restrict__ ei_raw) {
    int e = blockIdx.x * blockDim.x + threadIdx.x;
    if (e < NE) {
        int s, d;
        load_edge(ei_raw, e, s, d);
        if ((unsigned)d < NN && (unsigned)s < NN) {
            int pos = atomicAdd(&g_cursor[d], 1);
            if ((unsigned)pos < NE) g_col[pos] = s;
        }
    }
}

// ---------------------------------------------------------------------------
// GEMM v2:  g_h[N,96] = A[N,96] @ W[96,96];  A==nullptr -> read g_hp
// block=(32,8), 64-row tile. Inner loop vectorized over k:
//   - x loaded as warp-uniform float4 (1 broadcast wavefront per 4 k)
//   - per 4-k group: 8 vec-LDS + 12 scalar-LDS vs 96 FFMA (was 44 LDS)
// ---------------------------------------------------------------------------
__global__ void __launch_bounds__(256, 3)
k_gemm96(const float* __restrict__ A,
         const float* __restrict__ W) {
    __shared__ float xs[64][DD];     // 24 KB
    __shared__ float ws[32][DD];     // 12 KB
    const float* Ain = (A != nullptr) ? A : (const float*)g_hp;
    int row0 = blockIdx.x * 64;
    int tx = threadIdx.x, ty = threadIdx.y;
    int tid = ty * 32 + tx;

    for (int i = tid; i < 64 * DD; i += 256) {
        int r = i / DD, c = i % DD;
        int gr = row0 + r;
        xs[r][c] = (gr < NN) ? Ain[gr * DD + c] : 0.0f;
    }

    float acc[8][3];
#pragma unroll
    for (int r = 0; r < 8; r++) { acc[r][0] = 0.f; acc[r][1] = 0.f; acc[r][2] = 0.f; }

    for (int kb = 0; kb < DD; kb += 32) {
        __syncthreads();   // also covers initial xs load
        for (int i = tid; i < 32 * DD; i += 256) {
            int r = i / DD, c = i % DD;
            ws[r][c] = W[(kb + r) * DD + c];
        }
        __syncthreads();
#pragma unroll
        for (int k4 = 0; k4 < 32; k4 += 4) {
            // warp-uniform float4 loads: rows ty*8+r, 4 consecutive k
            float4 xv[8];
#pragma unroll
            for (int r = 0; r < 8; r++)
                xv[r] = *(const float4*)&xs[ty * 8 + r][kb + k4];
#pragma unroll
            for (int kk = 0; kk < 4; kk++) {
                float w0 = ws[k4 + kk][tx];
                float w1 = ws[k4 + kk][tx + 32];
                float w2 = ws[k4 + kk][tx + 64];
#pragma unroll
                for (int r = 0; r < 8; r++) {
                    float xvk = (kk == 0) ? xv[r].x :
                                (kk == 1) ? xv[r].y :
                                (kk == 2) ? xv[r].z : xv[r].w;
                    acc[r][0] = fmaf(xvk, w0, acc[r][0]);
                    acc[r][1] = fmaf(xvk, w1, acc[r][1]);
                    acc[r][2] = fmaf(xvk, w2, acc[r][2]);
                }
            }
        }
    }

#pragma unroll
    for (int r = 0; r < 8; r++) {
        int gr = row0 + ty * 8 + r;
        if (gr < NN) {
            g_h[gr * DD + tx]      = acc[r][0];
            g_h[gr * DD + tx + 32] = acc[r][1];
            g_h[gr * DD + tx + 64] = acc[r][2];
        }
    }
}

// ---------------------------------------------------------------------------
// Aggregation (unchanged): warp-per-node, float4 gathers, shuffle bcast.
// ---------------------------------------------------------------------------
__global__ void k_agg(const float* __restrict__ bias,
                      const float* __restrict__ a1,
                      int use_prelu,
                      float* __restrict__ out) {
    int gwarp = (blockIdx.x * blockDim.x + threadIdx.x) >> 5;
    int lane  = threadIdx.x & 31;
    if (gwarp >= NN) return;
    int node = gwarp;

    const float4* h4 = (const float4*)g_h;
    float4* dst4 = (out != nullptr) ? (float4*)out : (float4*)g_hp;

    float di = g_dinv[node];
    bool active = lane < D4;

    float4 acc = make_float4(0.f, 0.f, 0.f, 0.f);
    if (active) {
        float4 v = h4[node * D4 + lane];
        acc.x = di * v.x; acc.y = di * v.y; acc.z = di * v.z; acc.w = di * v.w;
    }

    int beg = g_rowptr[node];
    int end = g_rowptr[node + 1];

    for (int base = beg; base < end; base += 32) {
        int e = base + lane;
        int s = 0;
        float ns = 0.f;
        if (e < end) {
            s = g_col[e];
            ns = g_dinv[s];
        }
        int cnt = min(32, end - base);

        int j = 0;
        for (; j + 4 <= cnt; j += 4) {
            int   s0 = __shfl_sync(0xffffffffu, s,  j + 0);
            int   s1 = __shfl_sync(0xffffffffu, s,  j + 1);
            int   s2 = __shfl_sync(0xffffffffu, s,  j + 2);
            int   s3 = __shfl_sync(0xffffffffu, s,  j + 3);
            float n0 = __shfl_sync(0xffffffffu, ns, j + 0);
            float n1 = __shfl_sync(0xffffffffu, ns, j + 1);
            float n2 = __shfl_sync(0xffffffffu, ns, j + 2);
            float n3 = __shfl_sync(0xffffffffu, ns, j + 3);
            if (active) {
                float4 v0 = h4[s0 * D4 + lane];
                float4 v1 = h4[s1 * D4 + lane];
                float4 v2 = h4[s2 * D4 + lane];
                float4 v3 = h4[s3 * D4 + lane];
                acc.x = fmaf(n0, v0.x, acc.x); acc.y = fmaf(n0, v0.y, acc.y);
                acc.z = fmaf(n0, v0.z, acc.z); acc.w = fmaf(n0, v0.w, acc.w);
                acc.x = fmaf(n1, v1.x, acc.x); acc.y = fmaf(n1, v1.y, acc.y);
                acc.z = fmaf(n1, v1.z, acc.z); acc.w = fmaf(n1, v1.w, acc.w);
                acc.x = fmaf(n2, v2.x, acc.x); acc.y = fmaf(n2, v2.y, acc.y);
                acc.z = fmaf(n2, v2.z, acc.z); acc.w = fmaf(n2, v2.w, acc.w);
                acc.x = fmaf(n3, v3.x, acc.x); acc.y = fmaf(n3, v3.y, acc.y);
                acc.z = fmaf(n3, v3.z, acc.z); acc.w = fmaf(n3, v3.w, acc.w);
            }
        }
        for (; j < cnt; j++) {
            int   sj = __shfl_sync(0xffffffffu, s,  j);
            float nj = __shfl_sync(0xffffffffu, ns, j);
            if (active) {
                float4 v = h4[sj * D4 + lane];
                acc.x = fmaf(nj, v.x, acc.x); acc.y = fmaf(nj, v.y, acc.y);
                acc.z = fmaf(nj, v.z, acc.z); acc.w = fmaf(nj, v.w, acc.w);
            }
        }
    }

    if (active) {
        float4 b4 = ((const float4*)bias)[lane];
        float4 r;
        r.x = fmaf(di, acc.x, b4.x);
        r.y = fmaf(di, acc.y, b4.y);
        r.z = fmaf(di, acc.z, b4.z);
        r.w = fmaf(di, acc.w, b4.w);
        if (use_prelu) {
            float a = a1[0];
            r.x = r.x > 0.f ? r.x : a * r.x;
            r.y = r.y > 0.f ? r.y : a * r.y;
            r.z = r.z > 0.f ? r.z : a * r.z;
            r.w = r.w > 0.f ? r.w : a * r.w;
        }
        dst4[node * D4 + lane] = r;
    }
}

// ---------------------------------------------------------------------------
extern "C" void kernel_launch(void* const* d_in, const int* in_sizes, int n_in,
                              void* d_out, int out_size) {
    const float* x  = (const float*)d_in[0];
    const void*  ei = (const void*)d_in[1];
    const float* W1 = (const float*)d_in[2];
    const float* b1 = (const float*)d_in[3];
    const float* a1 = (const float*)d_in[4];
    const float* W2 = (const float*)d_in[5];
    const float* b2 = (const float*)d_in[6];
    float*       out = (float*)d_out;

    dim3 gB(32, 8);
    int gemmGrid = (NN + 63) / 64;
    int aggGrid = (NN + 7) / 8;   // warp per node, 8 warps/block

    // launch idx:  0         1         2            3 (profiled slot)
    k_init<<<(NN + 255) / 256, 256>>>();
    k_detect<<<1, DET_T>>>(ei);
    k_count_deg<<<(NE + 255) / 256, 256>>>(ei);
    k_gemm96<<<gemmGrid, gB>>>(x, W1);             // layer-1 GEMM (profiled)

    //              4                  5            6            7
    k_scanpartial_dinv<<<SCAN_NB, SCAN_B>>>();
    k_scan_offsets<<<1, 32>>>();
    k_scan_final<<<SCAN_NB, SCAN_B>>>();
    k_fill<<<(NE + 255) / 256, 256>>>(ei);

    //              8                  9            10
    k_agg<<<aggGrid, 256>>>(b1, a1, 1, nullptr);   // -> g_hp (PReLU)
    k_gemm96<<<gemmGrid, gB>>>(nullptr, W2);       // reads g_hp
    k_agg<<<aggGrid, 256>>>(b2, a1, 0, out);       // -> d_out
}

// round 11
// speedup vs baseline: 4.2850x; 1.0496x over previous
#include <cuda_runtime.h>
#include <cuda_bf16.h>

// Problem constants (fixed shapes from reference)
#define NN 50000
#define NE 800000
#define DD 96
#define D4 (DD / 4)   // 24 float4 per row

#define SCAN_B 1024
#define SCAN_NB ((NN + SCAN_B - 1) / SCAN_B)   // 49

// ---- device scratch (no runtime allocation allowed) ----
__device__ int   g_deg[NN];
__device__ float g_dinv[NN];
__device__ int   g_rowptr[NN + 1];
__device__ int   g_cursor[NN];
__device__ int   g_col[NE];
__device__ int   g_partial[SCAN_NB];
__device__ int   g_partoff[SCAN_NB];
__device__ int   g_is64;          // 1 if edge_index is int64, 0 if int32
__device__ float g_hp[NN * DD];   // layer-1 output (post bias+PReLU)

// ---------------------------------------------------------------------------
// init: degree = 1 (self loop). Block 0 additionally detects edge dtype by
// sampling 16K int64-slots: int32 data read as int64 packs two indices and
// lands outside [0,NN) with overwhelming probability per sample.
// ---------------------------------------------------------------------------
__global__ void k_init(const void* __restrict__ ei_raw) {
    int i = blockIdx.x * blockDim.x + threadIdx.x;
    if (i < NN) g_deg[i] = 1;

    if (blockIdx.x == 0) {
        __shared__ int bad;
        if (threadIdx.x == 0) bad = 0;
        __syncthreads();
        const long long* p64 = (const long long*)ei_raw;
        // 256 threads x 64 samples = 16K probes, stride ~48
        int stride = NE / (256 * 64);
        int myBad = 0;
        for (int j = 0; j < 64; j++) {
            int e = (threadIdx.x * 64 + j) * stride;
            if (e < NE) {
                long long v = p64[e];
                if (v < 0 || v >= NN) myBad = 1;
            }
        }
        if (myBad) atomicOr(&bad, 1);
        __syncthreads();
        if (threadIdx.x == 0) g_is64 = bad ? 0 : 1;
    }
}

__device__ __forceinline__ void load_edge(const void* ei_raw, int e, int& s, int& d) {
    if (g_is64) {
        const long long* p = (const long long*)ei_raw;
        s = (int)p[e];
        d = (int)p[NE + e];
    } else {
        const int* p = (const int*)ei_raw;
        s = p[e];
        d = p[NE + e];
    }
}

// ---------------------------------------------------------------------------
// degree count
// ---------------------------------------------------------------------------
__global__ void k_count_deg(const void* __restrict__ ei_raw) {
    int e = blockIdx.x * blockDim.x + threadIdx.x;
    if (e < NE) {
        int s, d;
        load_edge(ei_raw, e, s, d);
        if ((unsigned)d < NN) atomicAdd(&g_deg[d], 1);
    }
}

// ---------------------------------------------------------------------------
// fused: per-block sum of (deg-1) for scan, plus dinv = rsqrt(deg)
// ---------------------------------------------------------------------------
__global__ void k_scanpartial_dinv() {
    __shared__ int s[SCAN_B];
    int i = blockIdx.x * SCAN_B + threadIdx.x;
    int dg = (i < NN) ? g_deg[i] : 1;
    if (i < NN) g_dinv[i] = rsqrtf((float)dg);
    int v = (i < NN) ? (dg - 1) : 0;
    s[threadIdx.x] = v;
    __syncthreads();
    for (int off = SCAN_B / 2; off > 0; off >>= 1) {
        if (threadIdx.x < off) s[threadIdx.x] += s[threadIdx.x + off];
        __syncthreads();
    }
    if (threadIdx.x == 0) g_partial[blockIdx.x] = s[0];
}

// ---------------------------------------------------------------------------
// exclusive scan of the 49 block partials — single warp, shuffle scan
// ---------------------------------------------------------------------------
__global__ void k_scan_offsets() {
    int lane = threadIdx.x;           // one warp
    int v0 = (lane < SCAN_NB) ? g_partial[lane] : 0;
    int v1 = (32 + lane < SCAN_NB) ? g_partial[32 + lane] : 0;
    int i0 = v0;
#pragma unroll
    for (int off = 1; off < 32; off <<= 1) {
        int t = __shfl_up_sync(0xffffffffu, i0, off);
        if (lane >= off) i0 += t;
    }
    int total0 = __shfl_sync(0xffffffffu, i0, 31);
    int i1 = v1;
#pragma unroll
    for (int off = 1; off < 32; off <<= 1) {
        int t = __shfl_up_sync(0xffffffffu, i1, off);
        if (lane >= off) i1 += t;
    }
    if (lane < SCAN_NB) g_partoff[lane] = i0 - v0;
    if (32 + lane < SCAN_NB) g_partoff[32 + lane] = total0 + i1 - v1;
}

__global__ void k_scan_final() {
    __shared__ int s[SCAN_B];
    int i = blockIdx.x * SCAN_B + threadIdx.x;
    int v = (i < NN) ? (g_deg[i] - 1) : 0;
    s[threadIdx.x] = v;
    __syncthreads();
    for (int off = 1; off < SCAN_B; off <<= 1) {
        int t = 0;
        if ((int)threadIdx.x >= off) t = s[threadIdx.x - off];
        __syncthreads();
        s[threadIdx.x] += t;
        __syncthreads();
    }
    int inc = s[threadIdx.x];
    int base = g_partoff[blockIdx.x];
    if (i < NN) {
        g_rowptr[i] = base + inc - v;
        g_cursor[i] = base + inc - v;
    }
    if (i == NN - 1) g_rowptr[NN] = base + inc;
}

// ---------------------------------------------------------------------------
// CSR fill
// ---------------------------------------------------------------------------
__global__ void k_fill(const void* __restrict__ ei_raw) {
    int e = blockIdx.x * blockDim.x + threadIdx.x;
    if (e < NE) {
        int s, d;
        load_edge(ei_raw, e, s, d);
        if ((unsigned)d < NN && (unsigned)s < NN) {
            int pos = atomicAdd(&g_cursor[d], 1);
            if ((unsigned)pos < NE) g_col[pos] = s;
        }
    }
}

// ---------------------------------------------------------------------------
// FUSED LAYER:  out = act( (Dinv*A*Dinv @ Xin) @ W + b )
// Uses associativity: aggregate FIRST (inputs fully available at layer
// start), stage aggregated 64-row tile in smem, then GEMM from smem.
// Phase 1: warp w aggregates nodes row0+w*8 .. +8 into xs (float4 gathers,
//          shuffle-broadcast indices -- same scheme as the old k_agg).
// Phase 2: 64x96 @ 96x96 GEMM from xs (vectorized k), bias+PReLU epilogue.
// Xin == nullptr -> read g_hp; outp == nullptr -> write g_hp.
// ---------------------------------------------------------------------------
__global__ void __launch_bounds__(256, 3)
k_fused(const float* __restrict__ Xin,
        const float* __restrict__ W,
        const float* __restrict__ bias,
        const float* __restrict__ a1,
        int use_prelu,
        float* __restrict__ outp) {
    __shared__ float xs[64][DD];     // 24 KB: aggregated tile
    __shared__ float ws[32][DD];     // 12 KB: W k-chunk

    const float4* x4 = (Xin != nullptr) ? (const float4*)Xin : (const float4*)g_hp;
    float* dst = (outp != nullptr) ? outp : (float*)g_hp;

    int row0 = blockIdx.x * 64;
    int tid  = threadIdx.x;
    int warp = tid >> 5;
    int lane = tid & 31;
    bool activeF = lane < D4;        // 24 lanes carry the 96 features

    // ---------------- Phase 1: aggregate 8 nodes per warp ----------------
#pragma unroll 1
    for (int r = 0; r < 8; r++) {
        int node = row0 + warp * 8 + r;
        float4 acc = make_float4(0.f, 0.f, 0.f, 0.f);
        if (node < NN) {
            float di = g_dinv[node];
            if (activeF) {
                float4 v = x4[node * D4 + lane];
                acc.x = di * v.x; acc.y = di * v.y;
                acc.z = di * v.z; acc.w = di * v.w;
            }
            int beg = g_rowptr[node];
            int end = g_rowptr[node + 1];
            for (int base = beg; base < end; base += 32) {
                int e = base + lane;
                int s = 0;
                float ns = 0.f;
                if (e < end) {
                    s = g_col[e];
                    ns = g_dinv[s];
                }
                int cnt = min(32, end - base);
                int j = 0;
                for (; j + 4 <= cnt; j += 4) {
                    int   s0 = __shfl_sync(0xffffffffu, s,  j + 0);
                    int   s1 = __shfl_sync(0xffffffffu, s,  j + 1);
                    int   s2 = __shfl_sync(0xffffffffu, s,  j + 2);
                    int   s3 = __shfl_sync(0xffffffffu, s,  j + 3);
                    float n0 = __shfl_sync(0xffffffffu, ns, j + 0);
                    float n1 = __shfl_sync(0xffffffffu, ns, j + 1);
                    float n2 = __shfl_sync(0xffffffffu, ns, j + 2);
                    float n3 = __shfl_sync(0xffffffffu, ns, j + 3);
                    if (activeF) {
                        float4 v0 = x4[s0 * D4 + lane];
                        float4 v1 = x4[s1 * D4 + lane];
                        float4 v2 = x4[s2 * D4 + lane];
                        float4 v3 = x4[s3 * D4 + lane];
                        acc.x = fmaf(n0, v0.x, acc.x); acc.y = fmaf(n0, v0.y, acc.y);
                        acc.z = fmaf(n0, v0.z, acc.z); acc.w = fmaf(n0, v0.w, acc.w);
                        acc.x = fmaf(n1, v1.x, acc.x); acc.y = fmaf(n1, v1.y, acc.y);
                        acc.z = fmaf(n1, v1.z, acc.z); acc.w = fmaf(n1, v1.w, acc.w);
                        acc.x = fmaf(n2, v2.x, acc.x); acc.y = fmaf(n2, v2.y, acc.y);
                        acc.z = fmaf(n2, v2.z, acc.z); acc.w = fmaf(n2, v2.w, acc.w);
                        acc.x = fmaf(n3, v3.x, acc.x); acc.y = fmaf(n3, v3.y, acc.y);
                        acc.z = fmaf(n3, v3.z, acc.z); acc.w = fmaf(n3, v3.w, acc.w);
                    }
                }
                for (; j < cnt; j++) {
                    int   sj = __shfl_sync(0xffffffffu, s,  j);
                    float nj = __shfl_sync(0xffffffffu, ns, j);
                    if (activeF) {
                        float4 v = x4[sj * D4 + lane];
                        acc.x = fmaf(nj, v.x, acc.x); acc.y = fmaf(nj, v.y, acc.y);
                        acc.z = fmaf(nj, v.z, acc.z); acc.w = fmaf(nj, v.w, acc.w);
                    }
                }
            }
            // t = di * acc  (bias applied after GEMM now)
            acc.x *= di; acc.y *= di; acc.z *= di; acc.w *= di;
        }
        if (activeF)
            *(float4*)&xs[warp * 8 + r][lane * 4] = acc;
    }

    // ---------------- Phase 2: xs[64][96] @ W[96][96] ----------------
    int tx = lane;
    int ty = warp;

    float acc[8][3];
#pragma unroll
    for (int r = 0; r < 8; r++) { acc[r][0] = 0.f; acc[r][1] = 0.f; acc[r][2] = 0.f; }

    for (int kb = 0; kb < DD; kb += 32) {
        __syncthreads();   // first iteration: also closes phase 1
        for (int i = tid; i < 32 * DD; i += 256) {
            int r = i / DD, c = i % DD;
            ws[r][c] = W[(kb + r) * DD + c];
        }
        __syncthreads();
#pragma unroll
        for (int k4 = 0; k4 < 32; k4 += 4) {
            float4 xv[8];
#pragma unroll
            for (int r = 0; r < 8; r++)
                xv[r] = *(const float4*)&xs[ty * 8 + r][kb + k4];
#pragma unroll
            for (int kk = 0; kk < 4; kk++) {
                float w0 = ws[k4 + kk][tx];
                float w1 = ws[k4 + kk][tx + 32];
                float w2 = ws[k4 + kk][tx + 64];
#pragma unroll
                for (int r = 0; r < 8; r++) {
                    float xvk = (kk == 0) ? xv[r].x :
                                (kk == 1) ? xv[r].y :
                                (kk == 2) ? xv[r].z : xv[r].w;
                    acc[r][0] = fmaf(xvk, w0, acc[r][0]);
                    acc[r][1] = fmaf(xvk, w1, acc[r][1]);
                    acc[r][2] = fmaf(xvk, w2, acc[r][2]);
                }
            }
        }
    }

    // epilogue: bias + optional PReLU, store
    float b0 = bias[tx], b1 = bias[tx + 32], b2 = bias[tx + 64];
    float a = use_prelu ? a1[0] : 0.f;
#pragma unroll
    for (int r = 0; r < 8; r++) {
        int gr = row0 + ty * 8 + r;
        if (gr < NN) {
            float v0 = acc[r][0] + b0;
            float v1 = acc[r][1] + b1;
            float v2 = acc[r][2] + b2;
            if (use_prelu) {
                v0 = v0 > 0.f ? v0 : a * v0;
                v1 = v1 > 0.f ? v1 : a * v1;
                v2 = v2 > 0.f ? v2 : a * v2;
            }
            dst[gr * DD + tx]      = v0;
            dst[gr * DD + tx + 32] = v1;
            dst[gr * DD + tx + 64] = v2;
        }
    }
}

// ---------------------------------------------------------------------------
extern "C" void kernel_launch(void* const* d_in, const int* in_sizes, int n_in,
                              void* d_out, int out_size) {
    const float* x  = (const float*)d_in[0];
    const void*  ei = (const void*)d_in[1];
    const float* W1 = (const float*)d_in[2];
    const float* b1 = (const float*)d_in[3];
    const float* a1 = (const float*)d_in[4];
    const float* W2 = (const float*)d_in[5];
    const float* b2 = (const float*)d_in[6];
    float*       out = (float*)d_out;

    int fusedGrid = (NN + 63) / 64;   // 782

    // ---- graph structure prep ----
    k_init<<<(NN + 255) / 256, 256>>>(ei);
    k_count_deg<<<(NE + 255) / 256, 256>>>(ei);
    k_scanpartial_dinv<<<SCAN_NB, SCAN_B>>>();
    k_scan_offsets<<<1, 32>>>();
    k_scan_final<<<SCAN_NB, SCAN_B>>>();
    k_fill<<<(NE + 255) / 256, 256>>>(ei);

    // ---- layer 1: g_hp = PReLU( (Anorm @ x) @ W1 + b1 ) ----
    k_fused<<<fusedGrid, 256>>>(x, W1, b1, a1, 1, nullptr);

    // ---- layer 2: out = (Anorm @ g_hp) @ W2 + b2 ----
    k_fused<<<fusedGrid, 256>>>(nullptr, W2, b2, a1, 0, out);
}